// round 8
// baseline (speedup 1.0000x reference)
#include <cuda_runtime.h>
#include <cuda_fp16.h>
#include <cstdint>

// ---------------- problem constants ----------------
#define M_TOTAL 8192
#define N_TOTAL 4096
#define K_TOTAL 4096

// ---------------- GEMM tiling ----------------
#define BM 128
#define BN 128
#define BK 32                      // halfs of k per stage (two k16 MMA groups)
#define STAGES 4                   // power-of-2 ring
#define ROW_H 32                   // halfs per row per stage (64B rows, conflict-free)
#define A_STAGE_H (BM * ROW_H)     // 4096 halfs = 8KB
#define B_STAGE_H (BN * ROW_H)
#define SMEM_BYTES (STAGES * (A_STAGE_H + B_STAGE_H) * 2)   // 65536

// Scratch: fp16, fragment-permuted (layout as R5): within each 32-k block,
// thread t4's 16B at half-offset t4*8 holds its m16n8k16 fragment pairs for
// both k16 groups: {x=gr0lo, y=gr0hi, z=gr1lo, w=gr1hi}.
__device__ __half g_A[(size_t)M_TOTAL * K_TOTAL];   // 67 MB
__device__ __half g_WB[(size_t)N_TOTAL * K_TOTAL];  // 33.5 MB

// ---------------- fused prep kernel (unchanged) ----------------
#define NW_BLOCKS ((N_TOTAL * K_TOTAL) / 1024)   // 16384
#define NA_BLOCKS ((M_TOTAL * K_TOTAL) / 1024)   // 32768

__global__ __launch_bounds__(256)
void prep_kernel(const float* __restrict__ data,
                 const float* __restrict__ weight,
                 const float* __restrict__ w_mask) {
    __shared__ float f[1024];
    const int tid = threadIdx.x;
    const bool isW = blockIdx.x < NW_BLOCKS;
    const size_t base = isW ? (size_t)blockIdx.x * 1024
                            : (size_t)(blockIdx.x - NW_BLOCKS) * 1024;
    if (isW) {
        float4 v = reinterpret_cast<const float4*>(weight + base)[tid];
        float4 m = reinterpret_cast<const float4*>(w_mask + base)[tid];
        v.x *= m.x; v.y *= m.y; v.z *= m.z; v.w *= m.w;
        reinterpret_cast<float4*>(f)[tid] = v;
    } else {
        reinterpret_cast<float4*>(f)[tid] = reinterpret_cast<const float4*>(data + base)[tid];
    }
    __syncthreads();
    const int bb = tid >> 3;
    const int t  = (tid & 7) >> 1;
    const int gr = tid & 1;
    const int k0 = bb * 32 + gr * 16 + 2 * t;
    __half2 h0 = __floats2half2_rn(f[k0],     f[k0 + 1]);
    __half2 h1 = __floats2half2_rn(f[k0 + 8], f[k0 + 9]);
    __half* outp = isW ? g_WB : g_A;
    uint2 pk;
    pk.x = *reinterpret_cast<uint32_t*>(&h0);
    pk.y = *reinterpret_cast<uint32_t*>(&h1);
    reinterpret_cast<uint2*>(outp + base)[tid] = pk;
}

// ---------------- GEMM ----------------
__device__ __forceinline__ void cp_async16(void* dst, const void* src) {
    unsigned sdst = (unsigned)__cvta_generic_to_shared(dst);
    asm volatile("cp.async.cg.shared.global [%0], [%1], 16;" :: "r"(sdst), "l"(src));
}

// fp16-accumulate HMMA: C/D are 2 regs (4 halfs).
__device__ __forceinline__ void mma_f16_acc16(unsigned* c,
                                              unsigned a0, unsigned a1, unsigned a2, unsigned a3,
                                              unsigned b0, unsigned b1) {
    asm volatile(
        "mma.sync.aligned.m16n8k16.row.col.f16.f16.f16.f16 "
        "{%0,%1}, {%2,%3,%4,%5}, {%6,%7}, {%0,%1};"
        : "+r"(c[0]), "+r"(c[1])
        : "r"(a0), "r"(a1), "r"(a2), "r"(a3), "r"(b0), "r"(b1));
}

__global__ __launch_bounds__(256, 1)
void gemm_f16_kernel(float* __restrict__ out, const float* __restrict__ bias) {
    extern __shared__ __half smem[];
    __half* As = smem;                           // [STAGES][BM][ROW_H]
    __half* Bs = smem + STAGES * A_STAGE_H;      // [STAGES][BN][ROW_H]

    const int tid  = threadIdx.x;
    const int wid  = tid >> 5;
    const int lane = tid & 31;
    const int g    = lane >> 2;        // 0..7
    const int t4   = lane & 3;         // 0..3

    const int warp_m = (wid & 1) * 64;      // 0,64
    const int warp_n = (wid >> 1) * 32;     // 0,32,64,96

    const int bm = blockIdx.y * BM;
    const int bn = blockIdx.x * BN;

    const __half* Abase = g_A  + (size_t)bm * K_TOTAL;
    const __half* Bbase = g_WB + (size_t)bn * K_TOTAL;

    float facc[4][4][4];               // persistent fp32 accumulators
    unsigned hacc[4][4][2];            // fp16 span accumulators (half2 pairs)
    #pragma unroll
    for (int i = 0; i < 4; i++)
        #pragma unroll
        for (int j = 0; j < 4; j++) {
            #pragma unroll
            for (int r = 0; r < 4; r++) facc[i][j][r] = 0.0f;
            hacc[i][j][0] = 0u; hacc[i][j][1] = 0u;
        }

    const int aoff0 = (warp_m + g) * ROW_H + t4 * 8;
    const int boff0 = (warp_n + g) * ROW_H + t4 * 8;

    auto load_stage = [&](int kt) {
        const int buf = kt & (STAGES - 1);
        const int k0 = kt * BK;
        #pragma unroll
        for (int it = 0; it < 2; it++) {          // A
            int idx = tid + it * 256;
            int row = idx >> 2, ch = idx & 3;
            cp_async16(&As[buf * A_STAGE_H + row * ROW_H + ch * 8],
                       Abase + (size_t)row * K_TOTAL + k0 + ch * 8);
        }
        #pragma unroll
        for (int it = 0; it < 2; it++) {          // B
            int idx = tid + it * 256;
            int row = idx >> 2, ch = idx & 3;
            cp_async16(&Bs[buf * B_STAGE_H + row * ROW_H + ch * 8],
                       Bbase + (size_t)row * K_TOTAL + k0 + ch * 8);
        }
        asm volatile("cp.async.commit_group;");
    };

    load_stage(0);
    load_stage(1);
    load_stage(2);

    const int KT = K_TOTAL / BK;  // 128
    for (int kt = 0; kt < KT; ++kt) {
        asm volatile("cp.async.wait_group 2;");
        __syncthreads();
        if (kt + 3 < KT) {
            load_stage(kt + 3);
        } else {
            asm volatile("cp.async.commit_group;");
        }

        const int buf = kt & (STAGES - 1);
        const __half* Ab = &As[buf * A_STAGE_H];
        const __half* Bb = &Bs[buf * B_STAGE_H];

        uint4 bQ[4];
        #pragma unroll
        for (int j = 0; j < 4; j++)
            bQ[j] = *reinterpret_cast<const uint4*>(Bb + boff0 + j * 8 * ROW_H);

        #pragma unroll
        for (int i = 0; i < 4; i++) {
            uint4 a0 = *reinterpret_cast<const uint4*>(Ab + aoff0 + i * 16 * ROW_H);
            uint4 a1 = *reinterpret_cast<const uint4*>(Ab + aoff0 + i * 16 * ROW_H + 8 * ROW_H);
            #pragma unroll
            for (int j = 0; j < 4; j++) {
                mma_f16_acc16(hacc[i][j], a0.x, a1.x, a0.y, a1.y, bQ[j].x, bQ[j].y);
                mma_f16_acc16(hacc[i][j], a0.z, a1.z, a0.w, a1.w, bQ[j].z, bQ[j].w);
            }
        }

        // Promote fp16 span accumulators into fp32 every 4 chunks (span K=128).
        if ((kt & 3) == 3) {
            #pragma unroll
            for (int i = 0; i < 4; i++)
                #pragma unroll
                for (int j = 0; j < 4; j++) {
                    float2 lo = __half22float2(*reinterpret_cast<__half2*>(&hacc[i][j][0]));
                    float2 hi = __half22float2(*reinterpret_cast<__half2*>(&hacc[i][j][1]));
                    facc[i][j][0] += lo.x; facc[i][j][1] += lo.y;
                    facc[i][j][2] += hi.x; facc[i][j][3] += hi.y;
                    hacc[i][j][0] = 0u; hacc[i][j][1] = 0u;
                }
        }
    }

    // Epilogue: c0,c1 @ (g, 2t4/2t4+1); c2,c3 @ row g+8. float2 STG, bias fused.
    const int row0 = bm + warp_m;
    const int col0 = bn + warp_n;
    #pragma unroll
    for (int j = 0; j < 4; j++) {
        int c = col0 + j * 8 + t4 * 2;
        float b0 = __ldg(bias + c), b1 = __ldg(bias + c + 1);
        #pragma unroll
        for (int i = 0; i < 4; i++) {
            int r = row0 + i * 16 + g;
            float2 v0 = make_float2(facc[i][j][0] + b0, facc[i][j][1] + b1);
            float2 v1 = make_float2(facc[i][j][2] + b0, facc[i][j][3] + b1);
            *reinterpret_cast<float2*>(out + (size_t)r * N_TOTAL + c) = v0;
            *reinterpret_cast<float2*>(out + (size_t)(r + 8) * N_TOTAL + c) = v1;
        }
    }
}

extern "C" void kernel_launch(void* const* d_in, const int* in_sizes, int n_in,
                              void* d_out, int out_size) {
    const float* data   = (const float*)d_in[0];
    const float* weight = (const float*)d_in[1];
    const float* w_mask = (const float*)d_in[2];
    const float* bias_p = (const float*)d_in[3];
    float* out = (float*)d_out;

    prep_kernel<<<NW_BLOCKS + NA_BLOCKS, 256>>>(data, weight, w_mask);

    cudaFuncSetAttribute(gemm_f16_kernel,
                         cudaFuncAttributeMaxDynamicSharedMemorySize, SMEM_BYTES);
    dim3 grid(N_TOTAL / BN, M_TOTAL / BM);   // (32, 64)
    gemm_f16_kernel<<<grid, 256, SMEM_BYTES>>>(out, bias_p);
}

// round 10
// speedup vs baseline: 1.3657x; 1.3657x over previous
#include <cuda_runtime.h>
#include <cuda_fp16.h>
#include <cstdint>

// ---------------- problem constants ----------------
#define M_TOTAL 8192          // data rows (output rows)
#define N_TOTAL 4096          // W rows (output cols)
#define K_TOTAL 4096
#define KT_CNT  128           // K / 32

// ---------------- GEMM tiling: block = 128 n (W rows) x 128 m (data rows) ----------------
#define STAGES 4
#define A_ST_BYTES 4096       // 128 W-rows x 16 compressed halfs
#define B_ST_BYTES 8192       // 128 data-rows x 32 halfs
#define E_ST_BYTES 512        // 128 u32 metadata
#define OFF_B (STAGES * A_ST_BYTES)
#define OFF_E (OFF_B + STAGES * B_ST_BYTES)
#define SMEM_BYTES (OFF_E + STAGES * E_ST_BYTES)   // 51200 -> 2 CTAs/SM

#define RES_CAP (1u << 18)    // residual entry capacity (expected ~16k)

// ---------------- device scratch ----------------
__device__ __half   g_Bv [(size_t)M_TOTAL * K_TOTAL];        // data fp16, frag-permuted (B operand)
__device__ __half   g_dT [(size_t)K_TOTAL * M_TOTAL];        // data^T fp16 (residual gather)
__device__ __half   g_Ac [(size_t)N_TOTAL * (K_TOTAL / 2)];  // compressed W (2:4), frag-permuted
__device__ uint32_t g_meta[(size_t)N_TOTAL * KT_CNT];        // per (row, kchunk) 8 nibbles
__device__ uint32_t g_E  [(size_t)(N_TOTAL / 128) * KT_CNT * 128];  // assembled E regs
__device__ float    g_outT[(size_t)N_TOTAL * M_TOTAL];       // transposed output staging
__device__ uint32_t g_rn [RES_CAP];   // packed (n<<12)|k
__device__ float    g_rv [RES_CAP];
__device__ uint32_t g_srn[RES_CAP];   // sorted by n
__device__ float    g_srv[RES_CAP];
__device__ uint32_t g_rcnt;
__device__ uint32_t g_bins[N_TOTAL];
__device__ uint32_t g_start[N_TOTAL + 1];
__device__ uint32_t g_cursor[N_TOTAL];

// ---------------- reset ----------------
__global__ void rs_zero() {
    int i = blockIdx.x * blockDim.x + threadIdx.x;
    if (i < N_TOTAL) g_bins[i] = 0;
    if (i == 0) g_rcnt = 0;
}

// ---------------- prep: data -> g_Bv (fp16, B-fragment permuted) ----------------
// Within each 32-k block: k stored at pos = ((k>>1)&3)*8 + ((k>>3)<<1) + (k&1),
// so thread t4's LDS.128 at half-offset t4*8 yields b0..b3 = k {2t,2t+1},{+8},{+16},{+24}.
__global__ __launch_bounds__(256)
void prep_data(const float* __restrict__ data) {
    __shared__ float f[1024];
    const int tid = threadIdx.x;
    const size_t base = (size_t)blockIdx.x * 1024;
    reinterpret_cast<float4*>(f)[tid] = reinterpret_cast<const float4*>(data + base)[tid];
    __syncthreads();
    const int blk = tid >> 3;                 // 32-k block (0..31)
    const int p0  = (tid & 7) * 4;            // 4 consecutive permuted positions
    __half h[4];
    #pragma unroll
    for (int u = 0; u < 4; u++) {
        int p = p0 + u;
        int t = p >> 3, hh = (p & 7) >> 1, d = p & 1;
        int k = 8 * hh + 2 * t + d;
        h[u] = __float2half(f[blk * 32 + k]);
    }
    uint2 pk;
    pk.x = (uint32_t)__half_as_ushort(h[0]) | ((uint32_t)__half_as_ushort(h[1]) << 16);
    pk.y = (uint32_t)__half_as_ushort(h[2]) | ((uint32_t)__half_as_ushort(h[3]) << 16);
    reinterpret_cast<uint2*>(g_Bv)[base / 4 + tid] = pk;
}

// ---------------- prep: data -> g_dT (fp16 transpose) ----------------
__global__ __launch_bounds__(256)
void prep_dT(const float* __restrict__ data) {
    __shared__ float ts[32][33];
    const int tx = threadIdx.x, ty = threadIdx.y;
    const int k0 = blockIdx.x * 32, m0 = blockIdx.y * 32;
    #pragma unroll
    for (int i = 0; i < 4; i++)
        ts[ty + i * 8][tx] = data[(size_t)(m0 + ty + i * 8) * K_TOTAL + k0 + tx];
    __syncthreads();
    #pragma unroll
    for (int i = 0; i < 4; i++)
        g_dT[(size_t)(k0 + ty + i * 8) * M_TOTAL + m0 + tx] =
            __float2half(ts[tx][ty + i * 8]);
}

// ---------------- prep: W*mask -> 2:4 compressed + meta + residual ----------------
// One thread per (n, kchunk). Compressed col c -> pos = ((c>>1)&3)*4 + (c>>3)*2 + (c&1).
__global__ __launch_bounds__(128)
void prep_w(const float* __restrict__ w, const float* __restrict__ msk) {
    const int n  = blockIdx.x;
    const int kt = threadIdx.x;
    const float* wp = w   + (size_t)n * K_TOTAL + kt * 32;
    const float* mp = msk + (size_t)n * K_TOTAL + kt * 32;
    alignas(16) __half hh[16];
    uint32_t meta = 0;
    #pragma unroll
    for (int j = 0; j < 8; j++) {
        float v[4];
        int idx[4], cnt = 0;
        #pragma unroll
        for (int s = 0; s < 4; s++) {
            float mv = mp[j * 4 + s];
            float pv = wp[j * 4 + s] * mv;
            if (mv != 0.0f) { v[cnt] = pv; idx[cnt] = s; cnt++; }
        }
        int i0, i1; float v0, v1;
        if (cnt == 0)      { i0 = 0; i1 = 1; v0 = 0.f; v1 = 0.f; }
        else if (cnt == 1) {
            int p = idx[0];
            if (p == 3) { i0 = 2; i1 = 3; v0 = 0.f; v1 = v[0]; }
            else        { i0 = p; i1 = p + 1; v0 = v[0]; v1 = 0.f; }
        } else {
            i0 = idx[0]; i1 = idx[1]; v0 = v[0]; v1 = v[1];
            for (int s = 2; s < cnt; s++) {               // residual entries
                uint32_t pos = atomicAdd(&g_rcnt, 1u);
                if (pos < RES_CAP) {
                    g_rn[pos] = ((uint32_t)n << 12) | (uint32_t)(kt * 32 + j * 4 + idx[s]);
                    g_rv[pos] = v[s];
                }
            }
        }
        meta |= (uint32_t)(i0 | (i1 << 2)) << (4 * j);
        int c0 = 2 * j, c1 = 2 * j + 1;
        hh[((c0 >> 1) & 3) * 4 + (c0 >> 3) * 2 + (c0 & 1)] = __float2half(v0);
        hh[((c1 >> 1) & 3) * 4 + (c1 >> 3) * 2 + (c1 & 1)] = __float2half(v1);
    }
    uint4* dst = reinterpret_cast<uint4*>(g_Ac + (size_t)n * 2048 + kt * 16);
    dst[0] = reinterpret_cast<uint4*>(hh)[0];
    dst[1] = reinterpret_cast<uint4*>(hh)[1];
    g_meta[(size_t)n * KT_CNT + kt] = meta;
}

// ---------------- prep: assemble E registers ----------------
// g_E[(nb*KT + kt)*128 + p*2 + h]: pair p = (r/16)*8 + r%8 over rows (r, r+8);
// h = k-half. E = meta16(row r, half h) | meta16(row r+8, half h) << 16.
__global__ __launch_bounds__(256)
void prep_E() {
    int i = blockIdx.x * blockDim.x + threadIdx.x;       // 524288
    int nb = i >> 14, rem = i & 16383;
    int kt = rem >> 7, q = rem & 127;
    int p = q >> 1, h = q & 1;
    int r = (p >> 3) * 16 + (p & 7);
    int n0 = nb * 128 + r;
    uint32_t m0 = g_meta[(size_t)n0 * KT_CNT + kt];
    uint32_t m1 = g_meta[(size_t)(n0 + 8) * KT_CNT + kt];
    g_E[i] = ((m0 >> (16 * h)) & 0xFFFFu) | (((m1 >> (16 * h)) & 0xFFFFu) << 16);
}

// ---------------- residual sort by n ----------------
__global__ void rs_count() {
    uint32_t i = blockIdx.x * blockDim.x + threadIdx.x;
    if (i < g_rcnt && i < RES_CAP) atomicAdd(&g_bins[g_rn[i] >> 12], 1u);
}
__global__ __launch_bounds__(1024)
void rs_prefix() {
    __shared__ uint32_t ts[1024];
    int t = threadIdx.x;
    uint32_t loc[4], sum = 0;
    #pragma unroll
    for (int u = 0; u < 4; u++) { loc[u] = g_bins[t * 4 + u]; sum += loc[u]; }
    ts[t] = sum; __syncthreads();
    for (int off = 1; off < 1024; off <<= 1) {
        uint32_t v = (t >= off) ? ts[t - off] : 0; __syncthreads();
        ts[t] += v; __syncthreads();
    }
    uint32_t run = ts[t] - sum;
    #pragma unroll
    for (int u = 0; u < 4; u++) {
        g_start[t * 4 + u] = run; g_cursor[t * 4 + u] = run; run += loc[u];
    }
    if (t == 1023) g_start[N_TOTAL] = run;
}
__global__ void rs_scatter() {
    uint32_t i = blockIdx.x * blockDim.x + threadIdx.x;
    if (i < g_rcnt && i < RES_CAP) {
        uint32_t nk = g_rn[i];
        uint32_t pos = atomicAdd(&g_cursor[nk >> 12], 1u);
        g_srn[pos] = nk; g_srv[pos] = g_rv[i];
    }
}

// ---------------- sparse GEMM: outT = W_2:4 · data^T ----------------
__device__ __forceinline__ void cp_async16(void* dst, const void* src) {
    unsigned sdst = (unsigned)__cvta_generic_to_shared(dst);
    asm volatile("cp.async.cg.shared.global [%0], [%1], 16;" :: "r"(sdst), "l"(src));
}

__device__ __forceinline__ void mma_sp(float* c,
                                       unsigned a0, unsigned a1, unsigned a2, unsigned a3,
                                       const uint4& b, unsigned e) {
    asm volatile(
        "mma.sp::ordered_metadata.sync.aligned.m16n8k32.row.col.f32.f16.f16.f32 "
        "{%0,%1,%2,%3}, {%4,%5,%6,%7}, {%8,%9,%10,%11}, {%0,%1,%2,%3}, %12, 0x0;"
        : "+f"(c[0]), "+f"(c[1]), "+f"(c[2]), "+f"(c[3])
        : "r"(a0), "r"(a1), "r"(a2), "r"(a3),
          "r"(b.x), "r"(b.y), "r"(b.z), "r"(b.w), "r"(e));
}

__global__ __launch_bounds__(256, 2)
void gemm_sp_kernel() {
    extern __shared__ char smem[];
    char* As = smem;                 // [STAGES][128][32B]
    char* Bs = smem + OFF_B;         // [STAGES][128][64B]
    uint32_t* Es = reinterpret_cast<uint32_t*>(smem + OFF_E);  // [STAGES][128]

    const int tid  = threadIdx.x;
    const int wid  = tid >> 5;
    const int lane = tid & 31;
    const int g    = lane >> 2;
    const int t4   = lane & 3;

    const int wn = (wid & 1) * 64;       // W-row (output col) offset
    const int wm = (wid >> 1) * 32;      // data-row (output row) offset

    const int Nb = blockIdx.y * 128;
    const int Mb = blockIdx.x * 128;

    float acc[4][4][4];
    #pragma unroll
    for (int i = 0; i < 4; i++)
        #pragma unroll
        for (int j = 0; j < 4; j++)
            #pragma unroll
            for (int r = 0; r < 4; r++) acc[i][j][r] = 0.0f;

    auto load_stage = [&](int kt) {
        const int buf = kt & (STAGES - 1);
        {   // A: 256 x 16B
            int row = tid >> 1, hb = tid & 1;
            cp_async16(As + buf * A_ST_BYTES + row * 32 + hb * 16,
                       g_Ac + (size_t)(Nb + row) * 2048 + kt * 16 + hb * 8);
        }
        #pragma unroll
        for (int it = 0; it < 2; it++) {   // B: 512 x 16B
            int idx = tid + it * 256;
            int row = idx >> 2, ch = idx & 3;
            cp_async16(Bs + buf * B_ST_BYTES + row * 64 + ch * 16,
                       g_Bv + (size_t)(Mb + row) * K_TOTAL + kt * 32 + ch * 8);
        }
        if (tid < 32)                      // E: 32 x 16B
            cp_async16(reinterpret_cast<char*>(Es) + buf * E_ST_BYTES + tid * 16,
                       g_E + ((size_t)blockIdx.y * KT_CNT + kt) * 128 + tid * 4);
        asm volatile("cp.async.commit_group;");
    };

    load_stage(0);
    load_stage(1);
    load_stage(2);

    for (int kt = 0; kt < KT_CNT; ++kt) {
        asm volatile("cp.async.wait_group 2;");
        __syncthreads();
        if (kt + 3 < KT_CNT) load_stage(kt + 3);
        else asm volatile("cp.async.commit_group;");

        const int buf = kt & (STAGES - 1);
        const char* Ab = As + buf * A_ST_BYTES;
        const char* Bb = Bs + buf * B_ST_BYTES;
        const uint32_t* Eb = Es + buf * 128;

        uint4 bQ[4];
        #pragma unroll
        for (int j = 0; j < 4; j++)                       // FIX: half-offset t4*8 = byte t4*16
            bQ[j] = *reinterpret_cast<const uint4*>(Bb + (wm + j * 8 + g) * 64 + t4 * 16);

        #pragma unroll
        for (int i = 0; i < 4; i++) {
            int r = wn + i * 16 + g;
            uint2 ra = *reinterpret_cast<const uint2*>(Ab + r * 32 + t4 * 8);
            uint2 rb = *reinterpret_cast<const uint2*>(Ab + (r + 8) * 32 + t4 * 8);
            unsigned e = Eb[((wn >> 4) + i) * 16 + g * 2 + (t4 & 1)];
            #pragma unroll
            for (int j = 0; j < 4; j++)
                mma_sp(acc[i][j], ra.x, rb.x, ra.y, rb.y, bQ[j], e);
        }
    }

    // Epilogue: D(row = W-row n, col = data-row m). d0,d1 = (g, 2t4/2t4+1); d2,d3 = row g+8.
    #pragma unroll
    for (int i = 0; i < 4; i++) {
        int n0 = Nb + wn + i * 16 + g;
        #pragma unroll
        for (int j = 0; j < 4; j++) {
            int m0 = Mb + wm + j * 8 + 2 * t4;
            *reinterpret_cast<float2*>(g_outT + (size_t)n0 * M_TOTAL + m0) =
                make_float2(acc[i][j][0], acc[i][j][1]);
            *reinterpret_cast<float2*>(g_outT + (size_t)(n0 + 8) * M_TOTAL + m0) =
                make_float2(acc[i][j][2], acc[i][j][3]);
        }
    }
}

// ---------------- residual apply (on outT, coalesced along m) ----------------
__global__ __launch_bounds__(256)
void residual_apply() {
    const int n = blockIdx.x;
    const uint32_t s = g_start[n], e = g_start[n + 1];
    if (s == e) return;
    const int m0 = blockIdx.y * 2048;
    for (int it = 0; it < 8; it++) {
        int m = m0 + it * 256 + threadIdx.x;
        float acc = g_outT[(size_t)n * M_TOTAL + m];
        for (uint32_t q = s; q < e; q++) {
            int k = g_srn[q] & 0xFFF;
            acc += g_srv[q] * __half2float(g_dT[(size_t)k * M_TOTAL + m]);
        }
        g_outT[(size_t)n * M_TOTAL + m] = acc;
    }
}

// ---------------- finalize: transpose + bias ----------------
__global__ __launch_bounds__(256)
void finalize(float* __restrict__ out, const float* __restrict__ bias) {
    __shared__ float ts[32][33];
    const int tx = threadIdx.x, ty = threadIdx.y;
    const int m0 = blockIdx.x * 32, n0 = blockIdx.y * 32;
    #pragma unroll
    for (int i = 0; i < 4; i++)
        ts[ty + i * 8][tx] = g_outT[(size_t)(n0 + ty + i * 8) * M_TOTAL + m0 + tx];
    __syncthreads();
    const float b = __ldg(bias + n0 + tx);
    #pragma unroll
    for (int i = 0; i < 4; i++)
        out[(size_t)(m0 + ty + i * 8) * N_TOTAL + n0 + tx] = ts[tx][ty + i * 8] + b;
}

// ---------------- host ----------------
extern "C" void kernel_launch(void* const* d_in, const int* in_sizes, int n_in,
                              void* d_out, int out_size) {
    const float* data   = (const float*)d_in[0];
    const float* weight = (const float*)d_in[1];
    const float* w_mask = (const float*)d_in[2];
    const float* bias_p = (const float*)d_in[3];
    float* out = (float*)d_out;

    rs_zero<<<(N_TOTAL + 255) / 256, 256>>>();
    prep_data<<<(M_TOTAL * K_TOTAL) / 1024, 256>>>(data);
    prep_dT<<<dim3(K_TOTAL / 32, M_TOTAL / 32), dim3(32, 8)>>>(data);
    prep_w<<<N_TOTAL, 128>>>(weight, w_mask);
    prep_E<<<(N_TOTAL / 128) * KT_CNT * 128 / 256, 256>>>();
    rs_count<<<RES_CAP / 256, 256>>>();
    rs_prefix<<<1, 1024>>>();
    rs_scatter<<<RES_CAP / 256, 256>>>();

    cudaFuncSetAttribute(gemm_sp_kernel,
                         cudaFuncAttributeMaxDynamicSharedMemorySize, SMEM_BYTES);
    gemm_sp_kernel<<<dim3(M_TOTAL / 128, N_TOTAL / 128), 256, SMEM_BYTES>>>();

    residual_apply<<<dim3(N_TOTAL, M_TOTAL / 2048), 256>>>();
    finalize<<<dim3(M_TOTAL / 32, N_TOTAL / 32), dim3(32, 8)>>>(out, bias_p);
}